// round 14
// baseline (speedup 1.0000x reference)
#include <cuda_runtime.h>
#include <cuda_fp16.h>
#include <cstdint>
#include <math.h>

// Problem constants
#define BDIM 4
#define TDIM 4096
#define CDIM 1024
#define HDIM 2048
#define MTOT (BDIM * TDIM)   // 16384
#define NCH  32              // cumsum chunks
#define CLEN (TDIM / NCH)    // 128

// Scratch (device globals: allocation-free per harness rules)
__device__ __half g_s [(size_t)MTOT * HDIM];        // silu branch (fp16)
__device__ __half g_hh[(size_t)MTOT * 2 * HDIM];    // agg branch (fp16)
__device__ __half g_sh[(size_t)MTOT * HDIM];        // gated s*agg (fp16, GEMM3 A)
__device__ __half g_xh[(size_t)MTOT * CDIM];        // x fp16
__device__ __half g_wch[(size_t)3 * HDIM * CDIM];   // [W_sel|W_agg]^T fp16 [6144,K]
__device__ __half g_woh[(size_t)CDIM * HDIM];       // W_out^T fp16 [N,K]
__device__ float  g_part[BDIM * NCH * HDIM];        // cumsum partials

// ---------------------------------------------------------------------------
// PTX helpers (plain sm_80-era features only: compile under compute_103)
// ---------------------------------------------------------------------------
__device__ __forceinline__ void cpasync16(uint32_t saddr, const void* g) {
    asm volatile("cp.async.cg.shared.global [%0], [%1], 16;" :: "r"(saddr), "l"(g));
}
__device__ __forceinline__ void ldsm4(uint32_t* r, uint32_t saddr) {
    asm volatile("ldmatrix.sync.aligned.m8n8.x4.shared.b16 {%0,%1,%2,%3}, [%4];"
                 : "=r"(r[0]), "=r"(r[1]), "=r"(r[2]), "=r"(r[3]) : "r"(saddr));
}
__device__ __forceinline__ void mma_f16(float* c, const uint32_t* a,
                                        uint32_t b0, uint32_t b1) {
    asm volatile(
        "mma.sync.aligned.m16n8k16.row.col.f32.f16.f16.f32 "
        "{%0,%1,%2,%3}, {%4,%5,%6,%7}, {%8,%9}, {%0,%1,%2,%3};"
        : "+f"(c[0]), "+f"(c[1]), "+f"(c[2]), "+f"(c[3])
        : "r"(a[0]), "r"(a[1]), "r"(a[2]), "r"(a[3]), "r"(b0), "r"(b1));
}

// ---------------------------------------------------------------------------
// fp16 tensor-core GEMM: C[M,N] = A[M,K](fp16) @ Wt[N,K](fp16)^T.
// 256x128 CTA tile (512 thr, 16 warps 4x4, warp tile 64x32), BK=64 halves,
// 3-stage cp.async ring, multistage schedule (one barrier per k-tile).
// smem traffic: 45.7 KB/MFLOP (vs 61.4 for the 128x128 tile).
// EPI 1 = dual:   n<HDIM: s = silu(y*sqk_q)->C(fp16);  else h = y*sqk_k->C2(fp16)
// EPI 2 = plain fp32 -> C
// ---------------------------------------------------------------------------
constexpr int BM = 256, BN = 128, BKH = 64;
constexpr int KPAD = 72;                       // halves per padded row
constexpr int ROWB = KPAD * 2;                 // 144 bytes per row
constexpr int ATILE_B = BM * ROWB;             // 36864 bytes
constexpr int BTILE_B = BN * ROWB;             // 18432 bytes
constexpr int STAGE_B = ATILE_B + BTILE_B;     // 55296
constexpr int STAGES = 3;
constexpr int SMEM_BYTES = STAGES * STAGE_B;   // 165888 (<227KB)

template <int EPI, typename TO>
__global__ __launch_bounds__(512, 1)
void hgemm(const __half* __restrict__ A, const __half* __restrict__ Wt,
           TO* __restrict__ C, __half* __restrict__ C2,
           const float* __restrict__ sqk_q, const float* __restrict__ sqk_k,
           int M, int N, int K)
{
    extern __shared__ __half sm[];
    const uint32_t smb = (uint32_t)__cvta_generic_to_shared(sm);

    const int tid  = threadIdx.x;
    const int lane = tid & 31;
    const int wid  = tid >> 5;            // 0..15
    const int wm   = (wid >> 2) * 64;     // warp m offset (0,64,128,192)
    const int wn   = (wid & 3) * 32;      // warp n offset (0,32,64,96)
    const int bm   = blockIdx.y * BM;
    const int bn   = blockIdx.x * BN;
    const int nt   = K / BKH;

    // A ldmatrix.x4 lane offset: row = lane%16, kcol = (lane/16)*8 halves
    const uint32_t a_lane = (uint32_t)((lane & 15) * ROWB + (lane >> 4) * 16);
    // B ldmatrix.x4 lane offset
    const int bg = lane >> 3, br = lane & 7;
    const uint32_t b_lane = (uint32_t)(((bg >> 1) * 8 + br) * ROWB + (bg & 1) * 16);

    auto issue_tile = [&](int t, int s) {
        const int k0 = t * BKH;
        const uint32_t ab = smb + (uint32_t)s * STAGE_B;
        const uint32_t bb = ab + ATILE_B;
        // A tile: 256 rows x 8 chunks = 2048 chunks / 512 thr = 4 iters
#pragma unroll
        for (int i = 0; i < 4; ++i) {
            int idx = tid + (i << 9);
            int r = idx >> 3, c = idx & 7;
            cpasync16(ab + (uint32_t)(r * ROWB + c * 16),
                      A + (size_t)(bm + r) * K + k0 + c * 8);
        }
        // B tile: 128 rows x 8 chunks = 1024 chunks / 512 thr = 2 iters
#pragma unroll
        for (int i = 0; i < 2; ++i) {
            int idx = tid + (i << 9);
            int r = idx >> 3, c = idx & 7;
            cpasync16(bb + (uint32_t)(r * ROWB + c * 16),
                      Wt + (size_t)(bn + r) * K + k0 + c * 8);
        }
    };

    // Prologue: tiles 0 and 1 in flight; wait for tile 0.
    issue_tile(0, 0);
    asm volatile("cp.async.commit_group;");
    issue_tile(1, 1);
    asm volatile("cp.async.commit_group;");
    asm volatile("cp.async.wait_group 1;");
    __syncthreads();

    float acc[4][4][4];
#pragma unroll
    for (int i = 0; i < 4; ++i)
#pragma unroll
        for (int j = 0; j < 4; ++j)
#pragma unroll
            for (int q = 0; q < 4; ++q) acc[i][j][q] = 0.f;

    for (int t = 0; t < nt; ++t) {
        const int buf = t % STAGES;
        if (t + 2 < nt) issue_tile(t + 2, (t + 2) % STAGES);
        asm volatile("cp.async.commit_group;");

        const uint32_t ab = smb + (uint32_t)buf * STAGE_B;
        const uint32_t bb = ab + ATILE_B;
#pragma unroll
        for (int ks = 0; ks < 4; ++ks) {         // 4 x k16
            uint32_t af[4][4];
#pragma unroll
            for (int i = 0; i < 4; ++i)
                ldsm4(af[i], ab + (uint32_t)((wm + i * 16) * ROWB + ks * 32) + a_lane);
            uint32_t bf[2][4];
#pragma unroll
            for (int jj = 0; jj < 2; ++jj)
                ldsm4(bf[jj], bb + (uint32_t)((wn + jj * 16) * ROWB + ks * 32) + b_lane);
#pragma unroll
            for (int i = 0; i < 4; ++i) {
#pragma unroll
                for (int jj = 0; jj < 2; ++jj) {
                    mma_f16(acc[i][2 * jj],     af[i], bf[jj][0], bf[jj][1]);
                    mma_f16(acc[i][2 * jj + 1], af[i], bf[jj][2], bf[jj][3]);
                }
            }
        }

        asm volatile("cp.async.wait_group 1;");
        __syncthreads();
    }

    // Epilogue
    const int qr = lane >> 2;              // 0..7
    const int qc = (lane & 3) << 1;        // 0,2,4,6
    const bool is_s = (EPI == 1) && (bn < HDIM);   // block-uniform
    const float* sc = (EPI == 1) ? (is_s ? sqk_q : sqk_k - HDIM) : nullptr;
#pragma unroll
    for (int i = 0; i < 4; ++i) {
        const int m0 = bm + wm + i * 16 + qr;
#pragma unroll
        for (int j = 0; j < 4; ++j) {
            const int n0 = bn + wn + j * 8 + qc;
            float v0 = acc[i][j][0], v1 = acc[i][j][1];
            float v2 = acc[i][j][2], v3 = acc[i][j][3];
            if (EPI == 1) {
                float s0 = sc[n0], s1 = sc[n0 + 1];
                v0 *= s0; v1 *= s1; v2 *= s0; v3 *= s1;
                if (is_s) {
                    v0 = v0 / (1.f + __expf(-v0));
                    v1 = v1 / (1.f + __expf(-v1));
                    v2 = v2 / (1.f + __expf(-v2));
                    v3 = v3 / (1.f + __expf(-v3));
                }
                __half* dp = is_s
                    ? ((__half*)C + (size_t)m0 * HDIM + n0)
                    : (C2 + (size_t)m0 * (2 * HDIM) + (n0 - HDIM));
                size_t rstride = is_s ? HDIM : 2 * HDIM;
                *(__half2*)dp                  = __floats2half2_rn(v0, v1);
                *(__half2*)(dp + 8 * rstride)  = __floats2half2_rn(v2, v3);
            } else {
                *(float2*)((float*)C + (size_t)m0 * N + n0)       = make_float2(v0, v1);
                *(float2*)((float*)C + (size_t)(m0 + 8) * N + n0) = make_float2(v2, v3);
            }
        }
    }
}

// ---------------------------------------------------------------------------
// Preprocessing: fp32 -> fp16 convert, and transpose+convert [K,N] -> [N,K]
// ---------------------------------------------------------------------------
__global__ void cvt_half(const float4* __restrict__ in, __half2* __restrict__ out,
                         int n4)
{
    int i = blockIdx.x * blockDim.x + threadIdx.x;
    if (i < n4) {
        float4 v = in[i];
        out[2 * i]     = __floats2half2_rn(v.x, v.y);
        out[2 * i + 1] = __floats2half2_rn(v.z, v.w);
    }
}
__global__ void transpose_half(const float* __restrict__ in, __half* __restrict__ out,
                               int K, int N)   // in[K][N] fp32 -> out[N][K] fp16
{
    __shared__ float t[32][33];
    const int n0 = blockIdx.x * 32, k0 = blockIdx.y * 32;
    const int x = threadIdx.x, y = threadIdx.y;
#pragma unroll
    for (int j = 0; j < 32; j += 8)
        t[y + j][x] = in[(size_t)(k0 + y + j) * N + n0 + x];
    __syncthreads();
#pragma unroll
    for (int j = 0; j < 32; j += 8)
        out[(size_t)(n0 + y + j) * K + k0 + x] = __float2half_rn(t[x][y + j]);
}

// ---------------------------------------------------------------------------
// Cumsum (2-phase, half2-vectorized): poly = c0 + c0*c1.
// Phase 1: per-chunk partial sums. Phase 2: scan + causal mean + gate
//   sh = half(s * acc/(t+1))   (fp16 input for GEMM3)
// ---------------------------------------------------------------------------
__global__ void poly_partial(const __half2* __restrict__ h2,
                             float2* __restrict__ part2)
{
    const int ch2 = blockIdx.x * blockDim.x + threadIdx.x;   // 0..HDIM/2-1
    const int c  = blockIdx.y, b = blockIdx.z;
    const __half2* hp = h2 + ((size_t)b * TDIM + (size_t)c * CLEN) * HDIM + ch2;
    float2 acc = make_float2(0.f, 0.f);
#pragma unroll 4
    for (int t = 0; t < CLEN; ++t) {
        float2 c0 = __half22float2(hp[(size_t)t * HDIM]);
        float2 c1 = __half22float2(hp[(size_t)t * HDIM + HDIM / 2]);
        acc.x += fmaf(c0.x, c1.x, c0.x);
        acc.y += fmaf(c0.y, c1.y, c0.y);
    }
    part2[((size_t)b * NCH + c) * (HDIM / 2) + ch2] = acc;
}
__global__ void poly_scan_gate(const __half2* __restrict__ h2,
                               const float2* __restrict__ part2,
                               const __half2* __restrict__ s2,
                               __half2* __restrict__ sh2)
{
    const int ch2 = blockIdx.x * blockDim.x + threadIdx.x;
    const int c  = blockIdx.y, b = blockIdx.z;
    float2 acc = make_float2(0.f, 0.f);
    for (int c2 = 0; c2 < c; ++c2) {
        float2 p = part2[((size_t)b * NCH + c2) * (HDIM / 2) + ch2];
        acc.x += p.x; acc.y += p.y;
    }
    const __half2* hp = h2 + ((size_t)b * TDIM + (size_t)c * CLEN) * HDIM + ch2;
    const __half2* sp = s2 + ((size_t)b * TDIM + (size_t)c * CLEN) * (HDIM / 2) + ch2;
    __half2* op = sh2 + ((size_t)b * TDIM + (size_t)c * CLEN) * (HDIM / 2) + ch2;
    const int t0 = c * CLEN;
#pragma unroll 4
    for (int t = 0; t < CLEN; ++t) {
        float2 c0 = __half22float2(hp[(size_t)t * HDIM]);
        float2 c1 = __half22float2(hp[(size_t)t * HDIM + HDIM / 2]);
        acc.x += fmaf(c0.x, c1.x, c0.x);
        acc.y += fmaf(c0.y, c1.y, c0.y);
        float inv = 1.0f / (float)(t0 + t + 1);
        float2 sv = __half22float2(sp[(size_t)t * (HDIM / 2)]);
        op[(size_t)t * (HDIM / 2)] =
            __floats2half2_rn(sv.x * acc.x * inv, sv.y * acc.y * inv);
    }
}

// ---------------------------------------------------------------------------
// Launch
// ---------------------------------------------------------------------------
extern "C" void kernel_launch(void* const* d_in, const int* in_sizes, int n_in,
                              void* d_out, int out_size)
{
    const float* x     = (const float*)d_in[0];
    const float* W_sel = (const float*)d_in[1];
    const float* W_agg = (const float*)d_in[2];
    const float* W_out = (const float*)d_in[3];
    const float* sqk_q = (const float*)d_in[4];
    const float* sqk_k = (const float*)d_in[5];
    float* out = (float*)d_out;

    float* part;
    __half *s_p, *hh, *sh, *xh, *wch, *woh;
    cudaGetSymbolAddress((void**)&s_p, g_s);
    cudaGetSymbolAddress((void**)&hh, g_hh);
    cudaGetSymbolAddress((void**)&sh, g_sh);
    cudaGetSymbolAddress((void**)&xh, g_xh);
    cudaGetSymbolAddress((void**)&wch, g_wch);
    cudaGetSymbolAddress((void**)&woh, g_woh);
    cudaGetSymbolAddress((void**)&part, g_part);

    cudaFuncSetAttribute((const void*)hgemm<1, __half>,
                         cudaFuncAttributeMaxDynamicSharedMemorySize, SMEM_BYTES);
    cudaFuncSetAttribute((const void*)hgemm<2, float>,
                         cudaFuncAttributeMaxDynamicSharedMemorySize, SMEM_BYTES);

    // Preprocess: x -> fp16 ; weights -> transposed fp16 [N,K]
    {
        int n4 = MTOT * CDIM / 4;
        cvt_half<<<(n4 + 255) / 256, 256>>>((const float4*)x, (__half2*)xh, n4);
        dim3 tb(32, 8);
        // concat: rows [0,2048) = W_sel^T, rows [2048,6144) = W_agg^T
        transpose_half<<<dim3(HDIM / 32, CDIM / 32), tb>>>(W_sel, wch, CDIM, HDIM);
        transpose_half<<<dim3(2 * HDIM / 32, CDIM / 32), tb>>>(
            W_agg, wch + (size_t)HDIM * CDIM, CDIM, 2 * HDIM);
        transpose_half<<<dim3(CDIM / 32, HDIM / 32), tb>>>(W_out, woh, HDIM, CDIM);
    }

    dim3 blk(512);
    // Fused GEMM1+2: [s | h] = x @ [W_sel|W_agg], epilogue splits streams.
    // [16384 x 6144, K=1024] -> s fp16 (silu*sqk_q), h fp16 (*sqk_k)
    hgemm<1, __half><<<dim3(3 * HDIM / BN, MTOT / BM), blk, SMEM_BYTES>>>(
        xh, wch, s_p, hh, sqk_q, sqk_k, MTOT, 3 * HDIM, CDIM);
    // poly -> causal running mean -> gate      (fp32 math, fp16 out)
    poly_partial<<<dim3(HDIM / 2 / 256, NCH, BDIM), 256>>>(
        (const __half2*)hh, (float2*)part);
    poly_scan_gate<<<dim3(HDIM / 2 / 256, NCH, BDIM), 256>>>(
        (const __half2*)hh, (const float2*)part, (const __half2*)s_p, (__half2*)sh);
    // out = (s*agg) @ W_out                    [16384 x 1024, K=2048] -> fp32
    hgemm<2, float><<<dim3(CDIM / BN, MTOT / BM), blk, SMEM_BYTES>>>(
        sh, woh, out, nullptr, nullptr, nullptr, MTOT, CDIM, HDIM);
}

// round 15
// speedup vs baseline: 1.0678x; 1.0678x over previous
#include <cuda_runtime.h>
#include <cuda_fp16.h>
#include <cstdint>
#include <math.h>

// Problem constants
#define BDIM 4
#define TDIM 4096
#define CDIM 1024
#define HDIM 2048
#define MTOT (BDIM * TDIM)   // 16384
#define NCH  32              // cumsum chunks
#define CLEN (TDIM / NCH)    // 128

// Scratch (device globals: allocation-free per harness rules)
__device__ __half g_s [(size_t)MTOT * HDIM];        // silu branch (fp16)
__device__ __half g_hh[(size_t)MTOT * 2 * HDIM];    // agg branch (fp16)
__device__ __half g_sh[(size_t)MTOT * HDIM];        // gated s*agg (fp16, GEMM3 A)
__device__ __half g_xh[(size_t)MTOT * CDIM];        // x fp16
__device__ __half g_wch[(size_t)3 * HDIM * CDIM];   // [W_sel|W_agg]^T fp16 [6144,K]
__device__ __half g_woh[(size_t)CDIM * HDIM];       // W_out^T fp16 [N,K]
__device__ float  g_part[BDIM * NCH * HDIM];        // cumsum partials

// ---------------------------------------------------------------------------
// PTX helpers (plain sm_80-era features only: compile under compute_103)
// ---------------------------------------------------------------------------
__device__ __forceinline__ void cpasync16(uint32_t saddr, const void* g) {
    asm volatile("cp.async.cg.shared.global [%0], [%1], 16;" :: "r"(saddr), "l"(g));
}
__device__ __forceinline__ void ldsm4(uint32_t* r, uint32_t saddr) {
    asm volatile("ldmatrix.sync.aligned.m8n8.x4.shared.b16 {%0,%1,%2,%3}, [%4];"
                 : "=r"(r[0]), "=r"(r[1]), "=r"(r[2]), "=r"(r[3]) : "r"(saddr));
}
__device__ __forceinline__ void mma_f16(float* c, const uint32_t* a,
                                        uint32_t b0, uint32_t b1) {
    asm volatile(
        "mma.sync.aligned.m16n8k16.row.col.f32.f16.f16.f32 "
        "{%0,%1,%2,%3}, {%4,%5,%6,%7}, {%8,%9}, {%0,%1,%2,%3};"
        : "+f"(c[0]), "+f"(c[1]), "+f"(c[2]), "+f"(c[3])
        : "r"(a[0]), "r"(a[1]), "r"(a[2]), "r"(a[3]), "r"(b0), "r"(b1));
}

// ---------------------------------------------------------------------------
// fp16 tensor-core GEMM: C[M,N] = A[M,K](fp16) @ Wt[N,K](fp16)^T.
// 128x128 CTA tile (256 thr, 8 warps 2x4, warp tile 64x32), BK=64 halves,
// 3-stage cp.async ring, multistage schedule, one barrier per k-tile,
// 2 CTAs/SM. (Round-12 engine — best measured geometry.)
// EPI 1 = dual:  n<HDIM: s = silu(y*sqk_q)->C(fp16); else h = y*sqk_k->C2(fp16)
// EPI 2 = plain fp32 -> C
// ---------------------------------------------------------------------------
constexpr int BM = 128, BN = 128, BKH = 64;
constexpr int KPAD = 72;                       // halves per padded row
constexpr int ROWB = KPAD * 2;                 // 144 bytes per row
constexpr int ATILE_B = BM * ROWB;             // 18432 bytes
constexpr int STAGE_B = 2 * ATILE_B;           // A + B per stage (36864)
constexpr int STAGES = 3;
constexpr int SMEM_BYTES = STAGES * STAGE_B;   // 110592

template <int EPI, typename TO>
__global__ __launch_bounds__(256, 2)
void hgemm(const __half* __restrict__ A, const __half* __restrict__ Wt,
           TO* __restrict__ C, __half* __restrict__ C2,
           const float* __restrict__ sqk_q, const float* __restrict__ sqk_k,
           int M, int N, int K)
{
    extern __shared__ __half sm[];
    const uint32_t smb = (uint32_t)__cvta_generic_to_shared(sm);

    const int tid  = threadIdx.x;
    const int lane = tid & 31;
    const int wid  = tid >> 5;
    const int wm   = (wid >> 2) * 64;     // warp m offset
    const int wn   = (wid & 3) * 32;      // warp n offset
    const int bm   = blockIdx.y * BM;
    const int bn   = blockIdx.x * BN;
    const int nt   = K / BKH;

    // A ldmatrix.x4 lane offset: row = lane%16, kcol = (lane/16)*8 halves
    const uint32_t a_lane = (uint32_t)((lane & 15) * ROWB + (lane >> 4) * 16);
    // B ldmatrix.x4 lane offset
    const int bg = lane >> 3, br = lane & 7;
    const uint32_t b_lane = (uint32_t)(((bg >> 1) * 8 + br) * ROWB + (bg & 1) * 16);

    auto issue_tile = [&](int t, int s) {
        const int k0 = t * BKH;
        const uint32_t ab = smb + (uint32_t)s * STAGE_B;
        const uint32_t bb = ab + ATILE_B;
#pragma unroll
        for (int i = 0; i < 4; ++i) {
            int idx = tid + (i << 8);            // 0..1023
            int r = idx >> 3, c = idx & 7;
            uint32_t dst = (uint32_t)(r * ROWB + c * 16);
            cpasync16(ab + dst, A  + (size_t)(bm + r) * K + k0 + c * 8);
            cpasync16(bb + dst, Wt + (size_t)(bn + r) * K + k0 + c * 8);
        }
    };

    // Prologue: tiles 0 and 1 in flight; wait for tile 0.
    issue_tile(0, 0);
    asm volatile("cp.async.commit_group;");
    issue_tile(1, 1);
    asm volatile("cp.async.commit_group;");
    asm volatile("cp.async.wait_group 1;");
    __syncthreads();

    float acc[4][4][4];
#pragma unroll
    for (int i = 0; i < 4; ++i)
#pragma unroll
        for (int j = 0; j < 4; ++j)
#pragma unroll
            for (int q = 0; q < 4; ++q) acc[i][j][q] = 0.f;

    for (int t = 0; t < nt; ++t) {
        const int buf = t % STAGES;
        // Issue tile t+2 into the buffer consumed at iter t-1.
        if (t + 2 < nt) issue_tile(t + 2, (t + 2) % STAGES);
        asm volatile("cp.async.commit_group;");

        // Compute tile t.
        const uint32_t ab = smb + (uint32_t)buf * STAGE_B;
        const uint32_t bb = ab + ATILE_B;
#pragma unroll
        for (int ks = 0; ks < 4; ++ks) {         // 4 x k16
            uint32_t af[4][4];
#pragma unroll
            for (int i = 0; i < 4; ++i)
                ldsm4(af[i], ab + (uint32_t)((wm + i * 16) * ROWB + ks * 32) + a_lane);
            uint32_t bf[2][4];
#pragma unroll
            for (int jj = 0; jj < 2; ++jj)
                ldsm4(bf[jj], bb + (uint32_t)((wn + jj * 16) * ROWB + ks * 32) + b_lane);
#pragma unroll
            for (int i = 0; i < 4; ++i) {
#pragma unroll
                for (int jj = 0; jj < 2; ++jj) {
                    mma_f16(acc[i][2 * jj],     af[i], bf[jj][0], bf[jj][1]);
                    mma_f16(acc[i][2 * jj + 1], af[i], bf[jj][2], bf[jj][3]);
                }
            }
        }

        asm volatile("cp.async.wait_group 1;");
        __syncthreads();
    }

    // Epilogue
    const int qr = lane >> 2;              // 0..7
    const int qc = (lane & 3) << 1;        // 0,2,4,6
    const bool is_s = (EPI == 1) && (bn < HDIM);   // block-uniform
    const float* sc = (EPI == 1) ? (is_s ? sqk_q : sqk_k - HDIM) : nullptr;
#pragma unroll
    for (int i = 0; i < 4; ++i) {
        const int m0 = bm + wm + i * 16 + qr;
#pragma unroll
        for (int j = 0; j < 4; ++j) {
            const int n0 = bn + wn + j * 8 + qc;
            float v0 = acc[i][j][0], v1 = acc[i][j][1];
            float v2 = acc[i][j][2], v3 = acc[i][j][3];
            if (EPI == 1) {
                float s0 = sc[n0], s1 = sc[n0 + 1];
                v0 *= s0; v1 *= s1; v2 *= s0; v3 *= s1;
                if (is_s) {
                    v0 = v0 / (1.f + __expf(-v0));
                    v1 = v1 / (1.f + __expf(-v1));
                    v2 = v2 / (1.f + __expf(-v2));
                    v3 = v3 / (1.f + __expf(-v3));
                }
                __half* dp = is_s
                    ? ((__half*)C + (size_t)m0 * HDIM + n0)
                    : (C2 + (size_t)m0 * (2 * HDIM) + (n0 - HDIM));
                size_t rstride = is_s ? HDIM : 2 * HDIM;
                *(__half2*)dp                  = __floats2half2_rn(v0, v1);
                *(__half2*)(dp + 8 * rstride)  = __floats2half2_rn(v2, v3);
            } else {
                *(float2*)((float*)C + (size_t)m0 * N + n0)       = make_float2(v0, v1);
                *(float2*)((float*)C + (size_t)(m0 + 8) * N + n0) = make_float2(v2, v3);
            }
        }
    }
}

// ---------------------------------------------------------------------------
// Preprocessing: fp32 -> fp16 convert, and transpose+convert [K,N] -> [N,K]
// ---------------------------------------------------------------------------
__global__ void cvt_half(const float4* __restrict__ in, __half2* __restrict__ out,
                         int n4)
{
    int i = blockIdx.x * blockDim.x + threadIdx.x;
    if (i < n4) {
        float4 v = in[i];
        out[2 * i]     = __floats2half2_rn(v.x, v.y);
        out[2 * i + 1] = __floats2half2_rn(v.z, v.w);
    }
}
__global__ void transpose_half(const float* __restrict__ in, __half* __restrict__ out,
                               int K, int N)   // in[K][N] fp32 -> out[N][K] fp16
{
    __shared__ float t[32][33];
    const int n0 = blockIdx.x * 32, k0 = blockIdx.y * 32;
    const int x = threadIdx.x, y = threadIdx.y;
#pragma unroll
    for (int j = 0; j < 32; j += 8)
        t[y + j][x] = in[(size_t)(k0 + y + j) * N + n0 + x];
    __syncthreads();
#pragma unroll
    for (int j = 0; j < 32; j += 8)
        out[(size_t)(n0 + y + j) * K + k0 + x] = __float2half_rn(t[x][y + j]);
}

// ---------------------------------------------------------------------------
// Cumsum (2-phase, half2-vectorized): poly = c0 + c0*c1.
// Phase 1: per-chunk partial sums. Phase 2: scan + causal mean + gate
//   sh = half(s * acc/(t+1))   (fp16 input for GEMM3)
// ---------------------------------------------------------------------------
__global__ void poly_partial(const __half2* __restrict__ h2,
                             float2* __restrict__ part2)
{
    const int ch2 = blockIdx.x * blockDim.x + threadIdx.x;   // 0..HDIM/2-1
    const int c  = blockIdx.y, b = blockIdx.z;
    const __half2* hp = h2 + ((size_t)b * TDIM + (size_t)c * CLEN) * HDIM + ch2;
    float2 acc = make_float2(0.f, 0.f);
#pragma unroll 4
    for (int t = 0; t < CLEN; ++t) {
        float2 c0 = __half22float2(hp[(size_t)t * HDIM]);
        float2 c1 = __half22float2(hp[(size_t)t * HDIM + HDIM / 2]);
        acc.x += fmaf(c0.x, c1.x, c0.x);
        acc.y += fmaf(c0.y, c1.y, c0.y);
    }
    part2[((size_t)b * NCH + c) * (HDIM / 2) + ch2] = acc;
}
__global__ void poly_scan_gate(const __half2* __restrict__ h2,
                               const float2* __restrict__ part2,
                               const __half2* __restrict__ s2,
                               __half2* __restrict__ sh2)
{
    const int ch2 = blockIdx.x * blockDim.x + threadIdx.x;
    const int c  = blockIdx.y, b = blockIdx.z;
    float2 acc = make_float2(0.f, 0.f);
    for (int c2 = 0; c2 < c; ++c2) {
        float2 p = part2[((size_t)b * NCH + c2) * (HDIM / 2) + ch2];
        acc.x += p.x; acc.y += p.y;
    }
    const __half2* hp = h2 + ((size_t)b * TDIM + (size_t)c * CLEN) * HDIM + ch2;
    const __half2* sp = s2 + ((size_t)b * TDIM + (size_t)c * CLEN) * (HDIM / 2) + ch2;
    __half2* op = sh2 + ((size_t)b * TDIM + (size_t)c * CLEN) * (HDIM / 2) + ch2;
    const int t0 = c * CLEN;
#pragma unroll 4
    for (int t = 0; t < CLEN; ++t) {
        float2 c0 = __half22float2(hp[(size_t)t * HDIM]);
        float2 c1 = __half22float2(hp[(size_t)t * HDIM + HDIM / 2]);
        acc.x += fmaf(c0.x, c1.x, c0.x);
        acc.y += fmaf(c0.y, c1.y, c0.y);
        float inv = 1.0f / (float)(t0 + t + 1);
        float2 sv = __half22float2(sp[(size_t)t * (HDIM / 2)]);
        op[(size_t)t * (HDIM / 2)] =
            __floats2half2_rn(sv.x * acc.x * inv, sv.y * acc.y * inv);
    }
}

// ---------------------------------------------------------------------------
// Launch
// ---------------------------------------------------------------------------
extern "C" void kernel_launch(void* const* d_in, const int* in_sizes, int n_in,
                              void* d_out, int out_size)
{
    const float* x     = (const float*)d_in[0];
    const float* W_sel = (const float*)d_in[1];
    const float* W_agg = (const float*)d_in[2];
    const float* W_out = (const float*)d_in[3];
    const float* sqk_q = (const float*)d_in[4];
    const float* sqk_k = (const float*)d_in[5];
    float* out = (float*)d_out;

    float* part;
    __half *s_p, *hh, *sh, *xh, *wch, *woh;
    cudaGetSymbolAddress((void**)&s_p, g_s);
    cudaGetSymbolAddress((void**)&hh, g_hh);
    cudaGetSymbolAddress((void**)&sh, g_sh);
    cudaGetSymbolAddress((void**)&xh, g_xh);
    cudaGetSymbolAddress((void**)&wch, g_wch);
    cudaGetSymbolAddress((void**)&woh, g_woh);
    cudaGetSymbolAddress((void**)&part, g_part);

    cudaFuncSetAttribute((const void*)hgemm<1, __half>,
                         cudaFuncAttributeMaxDynamicSharedMemorySize, SMEM_BYTES);
    cudaFuncSetAttribute((const void*)hgemm<2, float>,
                         cudaFuncAttributeMaxDynamicSharedMemorySize, SMEM_BYTES);

    // Preprocess: x -> fp16 ; weights -> transposed fp16 [N,K]
    {
        int n4 = MTOT * CDIM / 4;
        cvt_half<<<(n4 + 255) / 256, 256>>>((const float4*)x, (__half2*)xh, n4);
        dim3 tb(32, 8);
        // concat: rows [0,2048) = W_sel^T, rows [2048,6144) = W_agg^T
        transpose_half<<<dim3(HDIM / 32, CDIM / 32), tb>>>(W_sel, wch, CDIM, HDIM);
        transpose_half<<<dim3(2 * HDIM / 32, CDIM / 32), tb>>>(
            W_agg, wch + (size_t)HDIM * CDIM, CDIM, 2 * HDIM);
        transpose_half<<<dim3(CDIM / 32, HDIM / 32), tb>>>(W_out, woh, HDIM, CDIM);
    }

    dim3 blk(256);
    // Fused GEMM1+2: [s | h] = x @ [W_sel|W_agg], epilogue splits streams.
    // [16384 x 6144, K=1024] -> s fp16 (silu*sqk_q), h fp16 (*sqk_k)
    hgemm<1, __half><<<dim3(3 * HDIM / BN, MTOT / BM), blk, SMEM_BYTES>>>(
        xh, wch, s_p, hh, sqk_q, sqk_k, MTOT, 3 * HDIM, CDIM);
    // poly -> causal running mean -> gate      (fp32 math, fp16 out)
    poly_partial<<<dim3(HDIM / 2 / 256, NCH, BDIM), 256>>>(
        (const __half2*)hh, (float2*)part);
    poly_scan_gate<<<dim3(HDIM / 2 / 256, NCH, BDIM), 256>>>(
        (const __half2*)hh, (const float2*)part, (const __half2*)s_p, (__half2*)sh);
    // out = (s*agg) @ W_out                    [16384 x 1024, K=2048] -> fp32
    hgemm<2, float><<<dim3(CDIM / BN, MTOT / BM), blk, SMEM_BYTES>>>(
        sh, woh, out, nullptr, nullptr, nullptr, MTOT, CDIM, HDIM);
}